// round 11
// baseline (speedup 1.0000x reference)
#include <cuda_runtime.h>
#include <cuda_bf16.h>
#include <math.h>

#define NB 8
#define SQL 1024
#define DM 1024
#define NH 16
#define HD 64
#define NTOK (NB*SQL)

// Q pre-scale: 1/sqrt(64) * log2(e)  (softmax done in base-2)
#define QSCL 0.1803368801111244f

// Scratch (no allocations allowed) — __device__ globals.
__device__ float    g_ln [NTOK*DM];         // LayerNorm(x) fp32, residual
__device__ unsigned g_lnb[NTOK*512];        // LayerNorm(x) bf16x2 (GEMM A)
__device__ unsigned g_qu [NB*NH*SQL*32];    // Q bf16x2, [b,h,s,d/2], pre-scaled QSCL
__device__ unsigned g_ku [NB*NH*SQL*32];    // K bf16x2
__device__ unsigned g_vu [NB*NH*SQL*32];    // V bf16x2
__device__ unsigned g_aob[NTOK*512];        // attention out bf16x2 (GEMM A)
__device__ unsigned g_wqkv[1024*1536];      // [Wq|Wkv] bf16x2, [k][n/2], n=3072
__device__ unsigned g_wob [1024*512];       // Wo bf16x2, [k][n/2], n=1024

__device__ __forceinline__ unsigned packbf(float lo, float hi){
    __nv_bfloat162 h = __floats2bfloat162_rn(lo, hi);
    return *reinterpret_cast<unsigned*>(&h);
}
__device__ __forceinline__ unsigned s2u(const void* p){
    return (unsigned)__cvta_generic_to_shared(p);
}
__device__ __forceinline__ float ex2f(float x){
    float y; asm("ex2.approx.ftz.f32 %0, %1;" : "=f"(y) : "f"(x)); return y;
}
__device__ __forceinline__ void mma_bf16(float* c, const unsigned* a, const unsigned* b){
    asm volatile(
        "mma.sync.aligned.m16n8k16.row.col.f32.bf16.bf16.f32 "
        "{%0,%1,%2,%3}, {%4,%5,%6,%7}, {%8,%9}, {%0,%1,%2,%3};\n"
        : "+f"(c[0]), "+f"(c[1]), "+f"(c[2]), "+f"(c[3])
        : "r"(a[0]), "r"(a[1]), "r"(a[2]), "r"(a[3]), "r"(b[0]), "r"(b[1]));
}
__device__ __forceinline__ void ldsm4(unsigned* r, unsigned addr){
    asm volatile("ldmatrix.sync.aligned.m8n8.x4.shared.b16 {%0,%1,%2,%3}, [%4];"
        : "=r"(r[0]), "=r"(r[1]), "=r"(r[2]), "=r"(r[3]) : "r"(addr));
}
__device__ __forceinline__ void ldsm4t(unsigned* r, unsigned addr){
    asm volatile("ldmatrix.sync.aligned.m8n8.x4.trans.shared.b16 {%0,%1,%2,%3}, [%4];"
        : "=r"(r[0]), "=r"(r[1]), "=r"(r[2]), "=r"(r[3]) : "r"(addr));
}
__device__ __forceinline__ void cpa16(unsigned saddr, const void* g){
    asm volatile("cp.async.cg.shared.global [%0], [%1], 16;" :: "r"(saddr), "l"(g) : "memory");
}
__device__ __forceinline__ void cpa_commit(){
    asm volatile("cp.async.commit_group;" ::: "memory");
}
template<int N> __device__ __forceinline__ void cpa_wait(){
    asm volatile("cp.async.wait_group %0;" :: "n"(N) : "memory");
}

// ---------------------------------------------------------------------------
// Fused prep: blocks 0..8191 do LayerNorm rows; blocks 8192..12287 convert
// weights fp32 -> bf16x2.
// ---------------------------------------------------------------------------
__global__ __launch_bounds__(256) void prep_kernel(const float* __restrict__ x,
                                                   const float* __restrict__ gamma,
                                                   const float* __restrict__ beta,
                                                   const float* __restrict__ Wq,
                                                   const float* __restrict__ Wkv,
                                                   const float* __restrict__ Wo)
{
    int tid = threadIdx.x;
    if (blockIdx.x >= NTOK){
        int id = (blockIdx.x - NTOK)*256 + tid;     // 0 .. 1048575, 4 elems each
        if (id < 786432){                           // qkv region: 1024 x 3072
            int e = id*4;
            int k = e / 3072, n = e % 3072;
            float4 v;
            if (n < 1024) v = *reinterpret_cast<const float4*>(Wq  + (size_t)k*1024 + n);
            else          v = *reinterpret_cast<const float4*>(Wkv + (size_t)k*2048 + (n-1024));
            uint2 u = { packbf(v.x, v.y), packbf(v.z, v.w) };
            *reinterpret_cast<uint2*>(&g_wqkv[(size_t)k*1536 + (n>>1)]) = u;
        } else {                                    // wo region: 1024 x 1024
            int e = (id - 786432)*4;
            float4 v = *reinterpret_cast<const float4*>(Wo + e);
            uint2 u = { packbf(v.x, v.y), packbf(v.z, v.w) };
            *reinterpret_cast<uint2*>(&g_wob[e>>1]) = u;
        }
        return;
    }

    int row = blockIdx.x;
    float4 v = reinterpret_cast<const float4*>(x + (size_t)row*DM)[tid];
    float s  = v.x+v.y+v.z+v.w;
    float ss = v.x*v.x+v.y*v.y+v.z*v.z+v.w*v.w;
    #pragma unroll
    for (int o=16;o;o>>=1){
        s  += __shfl_xor_sync(0xffffffffu, s,  o);
        ss += __shfl_xor_sync(0xffffffffu, ss, o);
    }
    __shared__ float ws[8], wss[8];
    int wid = tid>>5, lid = tid&31;
    if (lid==0){ ws[wid]=s; wss[wid]=ss; }
    __syncthreads();
    if (tid==0){
        float a=0.f,c=0.f;
        #pragma unroll
        for (int i=0;i<8;i++){ a+=ws[i]; c+=wss[i]; }
        ws[0]=a; wss[0]=c;
    }
    __syncthreads();
    float mean = ws[0]*(1.0f/DM);
    float var  = wss[0]*(1.0f/DM) - mean*mean;
    float rstd = rsqrtf(var + 1e-3f);
    float4 g  = reinterpret_cast<const float4*>(gamma)[tid];
    float4 bt = reinterpret_cast<const float4*>(beta)[tid];
    float4 o;
    o.x = (v.x-mean)*rstd*g.x + bt.x;
    o.y = (v.y-mean)*rstd*g.y + bt.y;
    o.z = (v.z-mean)*rstd*g.z + bt.z;
    o.w = (v.w-mean)*rstd*g.w + bt.w;
    reinterpret_cast<float4*>(g_ln + (size_t)row*DM)[tid] = o;
    uint2 u = { packbf(o.x, o.y), packbf(o.z, o.w) };
    *reinterpret_cast<uint2*>(&g_lnb[(size_t)row*512 + tid*2]) = u;
}

// ---------------------------------------------------------------------------
// bf16 pipelined GEMM, occupancy-first shape: C tile 128x64, 256 thr / 8 warps
// (4x2), warp tile 32x32, m16n8k16, ~85 regs -> 3 CTAs/SM (24 warps, 3
// independent barrier domains). cp.async 4-stage, prefetch distance 3.
// Smem chunk layouts (16B units): A: m*5 + k/8 (pad-5); B: k*9 + n/8 (pad-9).
// MODE 0: A=g_lnb, B=g_wqkv(ldn 3072) -> scatter Q(*QSCL)/K/V bf16.
// MODE 2: A=g_aob, B=g_wob(ldn 1024)  -> out = acc + bias + residual (fp32).
// ---------------------------------------------------------------------------
#define ABYTES 10240                 // 128 rows * 5 chunks * 16B
#define BBYTES 4608                  // 32 k * 9 chunks * 16B
#define SSTAGE (ABYTES + BBYTES)     // 14848
#define NSTAGE 4
#define GEMM_SMEM (NSTAGE*SSTAGE)    // 59392

template<int MODE>
__global__ void __launch_bounds__(256, 3) gemm_cp(const float* __restrict__ b1,
                                                  const float* __restrict__ b2,
                                                  float* __restrict__ Cout)
{
    extern __shared__ unsigned char smem_raw[];
    unsigned smem_u = s2u(smem_raw);

    const uint4* Ag = reinterpret_cast<const uint4*>((MODE==2) ? g_aob : g_lnb);
    const uint4* Bg = reinterpret_cast<const uint4*>((MODE==2) ? g_wob : g_wqkv);
    const int ldn4  = (MODE==2) ? 128 : 384;    // uint4 per weight row

    int tid  = threadIdx.x;
    int lane = tid & 31;
    int warp = tid >> 5;
    int wm = warp >> 1, wn = warp & 1;          // 4 x 2 warp grid
    int row0 = blockIdx.y * 128;
    int col0 = blockIdx.x * 64;
    int col4 = col0 >> 3;                       // in uint4

    float acc[2][4][4];
    #pragma unroll
    for (int i=0;i<2;i++)
        #pragma unroll
        for (int j=0;j<4;j++)
            #pragma unroll
            for (int e=0;e<4;e++) acc[i][j][e]=0.f;

    const int NKT = 32;

    // load tile kt into stage st: A 2 chunks/thread, B 1 chunk/thread
    #define LOAD_TILE(kt, st) do { \
        unsigned _ab = smem_u + (st)*SSTAGE; \
        unsigned _bb = _ab + ABYTES; \
        _Pragma("unroll") \
        for (int _i=0;_i<2;_i++){ \
            int _id = tid + _i*256; \
            int _m = _id>>2, _c = _id&3; \
            cpa16(_ab + (unsigned)((_m*5 + _c)*16), \
                  Ag + (size_t)(row0+_m)*128 + (kt)*4 + _c); \
        } \
        { \
            int _k = tid>>3, _c2 = tid&7; \
            cpa16(_bb + (unsigned)((_k*9 + _c2)*16), \
                  Bg + (size_t)((kt)*32+_k)*ldn4 + col4 + _c2); \
        } \
        cpa_commit(); \
    } while(0)

    // ---- prologue: stages 0,1,2
    LOAD_TILE(0, 0);
    LOAD_TILE(1, 1);
    LOAD_TILE(2, 2);
    cpa_wait<2>();
    __syncthreads();

    int buf = 0;
    for (int kt = 0; kt < NKT; kt++){
        // ---- compute tile kt from stage buf
        unsigned abase = smem_u + buf*SSTAGE;
        unsigned bbase = abase + ABYTES;
        #pragma unroll
        for (int ks=0; ks<2; ks++){
            unsigned afr[2][4], bfr[2][4];
            #pragma unroll
            for (int mf=0; mf<2; mf++){
                int m0 = wm*32 + mf*16;
                ldsm4(afr[mf], abase +
                      (unsigned)((((m0 + (lane&15))*5) + ks*2 + (lane>>4))*16));
            }
            #pragma unroll
            for (int np=0; np<2; np++){
                ldsm4t(bfr[np], bbase +
                      (unsigned)(((ks*16 + (lane&15))*9 + wn*4 + np*2 + (lane>>4))*16));
            }
            #pragma unroll
            for (int mf=0; mf<2; mf++){
                #pragma unroll
                for (int np=0; np<2; np++){
                    mma_bf16(acc[mf][np*2  ], afr[mf], bfr[np]);
                    mma_bf16(acc[mf][np*2+1], afr[mf], bfr[np]+2);
                }
            }
        }

        // ---- prefetch tile kt+3 into stage (kt+3)%4 (readers of the old
        // content finished before the barrier at end of iteration kt-1)
        if (kt+3 < NKT)
            LOAD_TILE(kt+3, (kt+3)%NSTAGE);
        else
            cpa_commit();                      // keep group count uniform
        cpa_wait<2>();                         // tile kt+1 resident
        __syncthreads();
        buf = (buf+1)%NSTAGE;
    }
    #undef LOAD_TILE

    // ---- epilogue
    if (MODE == 2){
        #pragma unroll
        for (int mf=0; mf<2; mf++)
            #pragma unroll
            for (int nf=0; nf<4; nf++)
                #pragma unroll
                for (int e=0; e<4; e++){
                    int r = row0 + wm*32 + mf*16 + (lane>>2) + ((e>=2)?8:0);
                    int c = col0 + wn*32 + nf*8 + 2*(lane&3) + (e&1);
                    Cout[(size_t)r*DM + c] = acc[mf][nf][e] + b1[c] + g_ln[(size_t)r*DM + c];
                }
    } else {
        #pragma unroll
        for (int mf=0; mf<2; mf++){
            #pragma unroll
            for (int nf=0; nf<4; nf++){
                int c = col0 + wn*32 + nf*8 + 2*(lane&3);
                #pragma unroll
                for (int half=0; half<2; half++){
                    int r = row0 + wm*32 + mf*16 + (lane>>2) + half*8;
                    int bb = r >> 10, sIdx = r & 1023;
                    float v0 = acc[mf][nf][half*2+0];
                    float v1 = acc[mf][nf][half*2+1];
                    if (c < 1024){
                        unsigned u = packbf((v0 + b1[c])*QSCL, (v1 + b1[c+1])*QSCL);
                        int h = c>>6, d = c&63;
                        g_qu[(((size_t)(bb*NH+h))*SQL + sIdx)*32 + (d>>1)] = u;
                    } else if (c < 2048){
                        int cc = c-1024;
                        unsigned u = packbf(v0 + b2[cc], v1 + b2[cc+1]);
                        int h = cc>>6, d = cc&63;
                        g_ku[(((size_t)(bb*NH+h))*SQL + sIdx)*32 + (d>>1)] = u;
                    } else {
                        int cc = c-2048;
                        unsigned u = packbf(v0 + b2[cc+1024], v1 + b2[cc+1025]);
                        int h = cc>>6, d = cc&63;
                        g_vu[(((size_t)(bb*NH+h))*SQL + sIdx)*32 + (d>>1)] = u;
                    }
                }
            }
        }
    }
}

// ---------------------------------------------------------------------------
// bf16 flash attention (round-9 version, unchanged).
// ---------------------------------------------------------------------------
#define ATSTR 36
#define TILE_KV (64*ATSTR)
#define ATT_SMEM (4*TILE_KV*4)             // 2 stages * (K+V) = 36864 B

__global__ __launch_bounds__(256) void attn_bf(const int* __restrict__ lens)
{
    extern __shared__ unsigned sm[];
    unsigned smem_u = s2u(sm);

    int bh = blockIdx.x;
    int qb = (int)(gridDim.y - 1 - blockIdx.y);    // heavy tiles first
    int b  = bh >> 4;
    int h  = bh & 15;
    int tid  = threadIdx.x;
    int lane = tid & 31;
    int w    = tid >> 5;
    int q0   = qb*128;
    int sub  = lane >> 3;
    int rr   = lane & 7;

    const uint4* kg = reinterpret_cast<const uint4*>(g_ku + (size_t)bh*SQL*32);
    const uint4* vg = reinterpret_cast<const uint4*>(g_vu + (size_t)bh*SQL*32);

    int len  = lens[b];
    int kmax = min(q0+127, len-1);
    int nkb  = (kmax>>6) + 1;

    {
        unsigned kb_s = smem_u;
        unsigned vb_s = smem_u + TILE_KV*4;
        #pragma unroll
        for (int i=0;i<2;i++){
            int id = tid + i*256;
            int r = id>>3, c = id&7;
            cpa16(kb_s + (unsigned)((r*ATSTR + c*4)*4), kg + (size_t)r*8 + c);
            cpa16(vb_s + (unsigned)((r*ATSTR + c*4)*4), vg + (size_t)r*8 + c);
        }
        cpa_commit();
    }

    int qrow0 = q0 + w*16 + (lane>>2);
    int qrow1 = qrow0 + 8;

    unsigned aQ[4][4];
    {
        const unsigned* q0p = g_qu + ((size_t)bh*SQL + qrow0)*32;
        const unsigned* q1p = g_qu + ((size_t)bh*SQL + qrow1)*32;
        #pragma unroll
        for (int ks=0; ks<4; ks++){
            aQ[ks][0] = q0p[ks*8 +     (lane&3)];
            aQ[ks][1] = q1p[ks*8 +     (lane&3)];
            aQ[ks][2] = q0p[ks*8 + 4 + (lane&3)];
            aQ[ks][3] = q1p[ks*8 + 4 + (lane&3)];
        }
    }

    float Oacc[8][4];
    #pragma unroll
    for (int i=0;i<8;i++)
        #pragma unroll
        for (int e=0;e<4;e++) Oacc[i][e]=0.f;
    float mi0=-1e30f, mi1=-1e30f, li0=0.f, li1=0.f;

    int buf = 0;
    for (int kb=0; kb<nkb; kb++){
        int k0 = kb*64;
        __syncthreads();
        if (kb+1 < nkb){
            int kn = (kb+1)*64;
            unsigned kb_s = smem_u + (unsigned)((buf^1)*(2*TILE_KV*4));
            unsigned vb_s = kb_s + TILE_KV*4;
            #pragma unroll
            for (int i=0;i<2;i++){
                int id = tid + i*256;
                int r = id>>3, c = id&7;
                cpa16(kb_s + (unsigned)((r*ATSTR + c*4)*4), kg + (size_t)(kn+r)*8 + c);
                cpa16(vb_s + (unsigned)((r*ATSTR + c*4)*4), vg + (size_t)(kn+r)*8 + c);
            }
        }
        cpa_commit();
        cpa_wait<1>();
        __syncthreads();

        unsigned kstage = smem_u + (unsigned)(buf*(2*TILE_KV*4));
        unsigned vstage = kstage + TILE_KV*4;

        float sc[8][4];
        #pragma unroll
        for (int nf=0; nf<8; nf++){
            sc[nf][0]=0.f; sc[nf][1]=0.f; sc[nf][2]=0.f; sc[nf][3]=0.f;
            unsigned kbase_a = kstage + (unsigned)(((nf*8 + rr)*ATSTR + sub*4)*4);
            #pragma unroll
            for (int ksp=0; ksp<2; ksp++){
                unsigned bb4[4];
                ldsm4(bb4, kbase_a + ksp*16*4);
                mma_bf16(sc[nf], aQ[2*ksp  ], bb4);
                mma_bf16(sc[nf], aQ[2*ksp+1], bb4+2);
            }
        }

        if (k0+63 > q0 + w*16 || k0+63 >= len){
            #pragma unroll
            for (int nf=0; nf<8; nf++){
                int jc = k0 + nf*8 + 2*(lane&3);
                #pragma unroll
                for (int e=0; e<4; e++){
                    int j   = jc + (e&1);
                    int row = (e>=2) ? qrow1 : qrow0;
                    sc[nf][e] = (j<=row && j<len) ? sc[nf][e] : -1e30f;
                }
            }
        }

        float rmax0=-1e30f, rmax1=-1e30f;
        #pragma unroll
        for (int nf=0; nf<8; nf++){
            rmax0 = fmaxf(rmax0, fmaxf(sc[nf][0], sc[nf][1]));
            rmax1 = fmaxf(rmax1, fmaxf(sc[nf][2], sc[nf][3]));
        }
        rmax0 = fmaxf(rmax0, __shfl_xor_sync(0xffffffffu, rmax0, 1));
        rmax0 = fmaxf(rmax0, __shfl_xor_sync(0xffffffffu, rmax0, 2));
        rmax1 = fmaxf(rmax1, __shfl_xor_sync(0xffffffffu, rmax1, 1));
        rmax1 = fmaxf(rmax1, __shfl_xor_sync(0xffffffffu, rmax1, 2));

        float mn0 = fmaxf(mi0, rmax0);
        float mn1 = fmaxf(mi1, rmax1);
        float corr0 = ex2f(mi0 - mn0);
        float corr1 = ex2f(mi1 - mn1);
        mi0 = mn0; mi1 = mn1;

        float rs0=0.f, rs1=0.f;
        #pragma unroll
        for (int nf=0; nf<8; nf++){
            sc[nf][0] = ex2f(sc[nf][0]-mn0);
            sc[nf][1] = ex2f(sc[nf][1]-mn0);
            sc[nf][2] = ex2f(sc[nf][2]-mn1);
            sc[nf][3] = ex2f(sc[nf][3]-mn1);
            rs0 += sc[nf][0]+sc[nf][1];
            rs1 += sc[nf][2]+sc[nf][3];
        }
        rs0 += __shfl_xor_sync(0xffffffffu, rs0, 1);
        rs0 += __shfl_xor_sync(0xffffffffu, rs0, 2);
        rs1 += __shfl_xor_sync(0xffffffffu, rs1, 1);
        rs1 += __shfl_xor_sync(0xffffffffu, rs1, 2);
        li0 = li0*corr0 + rs0;
        li1 = li1*corr1 + rs1;

        #pragma unroll
        for (int nf=0; nf<8; nf++){
            Oacc[nf][0]*=corr0; Oacc[nf][1]*=corr0;
            Oacc[nf][2]*=corr1; Oacc[nf][3]*=corr1;
        }

        #pragma unroll
        for (int ks=0; ks<4; ks++){
            unsigned aP[4];
            aP[0] = packbf(sc[2*ks  ][0], sc[2*ks  ][1]);
            aP[1] = packbf(sc[2*ks  ][2], sc[2*ks  ][3]);
            aP[2] = packbf(sc[2*ks+1][0], sc[2*ks+1][1]);
            aP[3] = packbf(sc[2*ks+1][2], sc[2*ks+1][3]);
            unsigned vrow = vstage + (unsigned)(((ks*16 + (sub&1)*8 + rr)*ATSTR + (sub>>1)*4)*4);
            #pragma unroll
            for (int dfp=0; dfp<4; dfp++){
                unsigned bb4[4];
                ldsm4t(bb4, vrow + dfp*8*4);
                mma_bf16(Oacc[2*dfp  ], aP, bb4);
                mma_bf16(Oacc[2*dfp+1], aP, bb4+2);
            }
        }
        buf ^= 1;
    }

    float inv0 = 1.f/li0, inv1 = 1.f/li1;
    unsigned* o0 = g_aob + ((size_t)(b*SQL + qrow0))*512 + h*32;
    unsigned* o1 = g_aob + ((size_t)(b*SQL + qrow1))*512 + h*32;
    #pragma unroll
    for (int df=0; df<8; df++){
        o0[df*4 + (lane&3)] = packbf(Oacc[df][0]*inv0, Oacc[df][1]*inv0);
        o1[df*4 + (lane&3)] = packbf(Oacc[df][2]*inv1, Oacc[df][3]*inv1);
    }
}

// ---------------------------------------------------------------------------
extern "C" void kernel_launch(void* const* d_in, const int* in_sizes, int n_in,
                              void* d_out, int out_size)
{
    const float* x     = (const float*)d_in[0];
    const int*   lens  = (const int*)  d_in[2];
    const float* Wq    = (const float*)d_in[3];
    const float* bq    = (const float*)d_in[4];
    const float* Wkv   = (const float*)d_in[5];
    const float* bkv   = (const float*)d_in[6];
    const float* Wo    = (const float*)d_in[7];
    const float* bo    = (const float*)d_in[8];
    const float* gamma = (const float*)d_in[9];
    const float* beta  = (const float*)d_in[10];
    float* out = (float*)d_out;

    cudaFuncSetAttribute(gemm_cp<0>, cudaFuncAttributeMaxDynamicSharedMemorySize, GEMM_SMEM);
    cudaFuncSetAttribute(gemm_cp<2>, cudaFuncAttributeMaxDynamicSharedMemorySize, GEMM_SMEM);
    cudaFuncSetAttribute(attn_bf,    cudaFuncAttributeMaxDynamicSharedMemorySize, ATT_SMEM);

    prep_kernel<<<NTOK + 4096, 256>>>(x, gamma, beta, Wq, Wkv, Wo);
    gemm_cp<0><<<dim3(48,64), 256, GEMM_SMEM>>>(bq, bkv, nullptr);
    attn_bf   <<<dim3(128,8), 256, ATT_SMEM>>>(lens);
    gemm_cp<2><<<dim3(16,64), 256, GEMM_SMEM>>>(bo, nullptr, out);
}

// round 12
// speedup vs baseline: 1.1300x; 1.1300x over previous
#include <cuda_runtime.h>
#include <cuda_bf16.h>
#include <math.h>

#define NB 8
#define SQL 1024
#define DM 1024
#define NH 16
#define HD 64
#define NTOK (NB*SQL)

// Q pre-scale: 1/sqrt(64) * log2(e)  (softmax done in base-2)
#define QSCL 0.1803368801111244f

// Scratch (no allocations allowed) — __device__ globals.
__device__ float    g_ln [NTOK*DM];         // LayerNorm(x) fp32, residual
__device__ unsigned g_lnb[NTOK*512];        // LayerNorm(x) bf16x2 (GEMM A)
__device__ unsigned g_qu [NB*NH*SQL*32];    // Q bf16x2, [b,h,s,d/2], pre-scaled QSCL
__device__ unsigned g_ku [NB*NH*SQL*32];    // K bf16x2
__device__ unsigned g_vu [NB*NH*SQL*32];    // V bf16x2
__device__ unsigned g_aob[NTOK*512];        // attention out bf16x2 (GEMM A)
__device__ unsigned g_wqkv[1024*1536];      // [Wq|Wkv] bf16x2, [k][n/2], n=3072
__device__ unsigned g_wob [1024*512];       // Wo bf16x2, [k][n/2], n=1024

__device__ __forceinline__ unsigned packbf(float lo, float hi){
    __nv_bfloat162 h = __floats2bfloat162_rn(lo, hi);
    return *reinterpret_cast<unsigned*>(&h);
}
__device__ __forceinline__ unsigned s2u(const void* p){
    return (unsigned)__cvta_generic_to_shared(p);
}
__device__ __forceinline__ float ex2f(float x){
    float y; asm("ex2.approx.ftz.f32 %0, %1;" : "=f"(y) : "f"(x)); return y;
}
__device__ __forceinline__ void mma_bf16(float* c, const unsigned* a, const unsigned* b){
    asm volatile(
        "mma.sync.aligned.m16n8k16.row.col.f32.bf16.bf16.f32 "
        "{%0,%1,%2,%3}, {%4,%5,%6,%7}, {%8,%9}, {%0,%1,%2,%3};\n"
        : "+f"(c[0]), "+f"(c[1]), "+f"(c[2]), "+f"(c[3])
        : "r"(a[0]), "r"(a[1]), "r"(a[2]), "r"(a[3]), "r"(b[0]), "r"(b[1]));
}
__device__ __forceinline__ void ldsm4(unsigned* r, unsigned addr){
    asm volatile("ldmatrix.sync.aligned.m8n8.x4.shared.b16 {%0,%1,%2,%3}, [%4];"
        : "=r"(r[0]), "=r"(r[1]), "=r"(r[2]), "=r"(r[3]) : "r"(addr));
}
__device__ __forceinline__ void ldsm4t(unsigned* r, unsigned addr){
    asm volatile("ldmatrix.sync.aligned.m8n8.x4.trans.shared.b16 {%0,%1,%2,%3}, [%4];"
        : "=r"(r[0]), "=r"(r[1]), "=r"(r[2]), "=r"(r[3]) : "r"(addr));
}
__device__ __forceinline__ void cpa16(unsigned saddr, const void* g){
    asm volatile("cp.async.cg.shared.global [%0], [%1], 16;" :: "r"(saddr), "l"(g) : "memory");
}
__device__ __forceinline__ void cpa_commit(){
    asm volatile("cp.async.commit_group;" ::: "memory");
}
template<int N> __device__ __forceinline__ void cpa_wait(){
    asm volatile("cp.async.wait_group %0;" :: "n"(N) : "memory");
}
__device__ __forceinline__ void stg_cs_f2(float* p, float2 v){
    asm volatile("st.global.cs.v2.f32 [%0], {%1, %2};" :: "l"(p), "f"(v.x), "f"(v.y) : "memory");
}

// ---------------------------------------------------------------------------
// Fused prep: blocks 0..8191 do LayerNorm rows; blocks 8192..12287 convert
// weights fp32 -> bf16x2.
// ---------------------------------------------------------------------------
__global__ __launch_bounds__(256) void prep_kernel(const float* __restrict__ x,
                                                   const float* __restrict__ gamma,
                                                   const float* __restrict__ beta,
                                                   const float* __restrict__ Wq,
                                                   const float* __restrict__ Wkv,
                                                   const float* __restrict__ Wo)
{
    int tid = threadIdx.x;
    if (blockIdx.x >= NTOK){
        int id = (blockIdx.x - NTOK)*256 + tid;     // 0 .. 1048575, 4 elems each
        if (id < 786432){                           // qkv region: 1024 x 3072
            int e = id*4;
            int k = e / 3072, n = e % 3072;
            float4 v;
            if (n < 1024) v = *reinterpret_cast<const float4*>(Wq  + (size_t)k*1024 + n);
            else          v = *reinterpret_cast<const float4*>(Wkv + (size_t)k*2048 + (n-1024));
            uint2 u = { packbf(v.x, v.y), packbf(v.z, v.w) };
            *reinterpret_cast<uint2*>(&g_wqkv[(size_t)k*1536 + (n>>1)]) = u;
        } else {                                    // wo region: 1024 x 1024
            int e = (id - 786432)*4;
            float4 v = *reinterpret_cast<const float4*>(Wo + e);
            uint2 u = { packbf(v.x, v.y), packbf(v.z, v.w) };
            *reinterpret_cast<uint2*>(&g_wob[e>>1]) = u;
        }
        return;
    }

    int row = blockIdx.x;
    float4 v = reinterpret_cast<const float4*>(x + (size_t)row*DM)[tid];
    float s  = v.x+v.y+v.z+v.w;
    float ss = v.x*v.x+v.y*v.y+v.z*v.z+v.w*v.w;
    #pragma unroll
    for (int o=16;o;o>>=1){
        s  += __shfl_xor_sync(0xffffffffu, s,  o);
        ss += __shfl_xor_sync(0xffffffffu, ss, o);
    }
    __shared__ float ws[8], wss[8];
    int wid = tid>>5, lid = tid&31;
    if (lid==0){ ws[wid]=s; wss[wid]=ss; }
    __syncthreads();
    if (tid==0){
        float a=0.f,c=0.f;
        #pragma unroll
        for (int i=0;i<8;i++){ a+=ws[i]; c+=wss[i]; }
        ws[0]=a; wss[0]=c;
    }
    __syncthreads();
    float mean = ws[0]*(1.0f/DM);
    float var  = wss[0]*(1.0f/DM) - mean*mean;
    float rstd = rsqrtf(var + 1e-3f);
    float4 g  = reinterpret_cast<const float4*>(gamma)[tid];
    float4 bt = reinterpret_cast<const float4*>(beta)[tid];
    float4 o;
    o.x = (v.x-mean)*rstd*g.x + bt.x;
    o.y = (v.y-mean)*rstd*g.y + bt.y;
    o.z = (v.z-mean)*rstd*g.z + bt.z;
    o.w = (v.w-mean)*rstd*g.w + bt.w;
    reinterpret_cast<float4*>(g_ln + (size_t)row*DM)[tid] = o;
    uint2 u = { packbf(o.x, o.y), packbf(o.z, o.w) };
    *reinterpret_cast<uint2*>(&g_lnb[(size_t)row*512 + tid*2]) = u;
}

// ---------------------------------------------------------------------------
// bf16 pipelined GEMM (R9 config): 128x128x32 tiles, 256 thr / 8 warps (2x4),
// warp tile 64x32, m16n8k16, cp.async 4-stage, compute-then-prefetch,
// one barrier per k-tile, prefetch distance 3.
// Smem (16B units): A: m*5+k/8 (pad-5); B: k*17+n/8 (pad-17).
// MODE 0: A=g_lnb, B=g_wqkv(ldn 3072) -> scatter Q(*QSCL)/K/V bf16.
// MODE 2: A=g_aob, B=g_wob(ldn 1024)  -> out = acc + bias + residual (f32,
//         float2-vectorized, streaming stores).
// ---------------------------------------------------------------------------
#define SSTAGE 18944                 // bytes per stage: A 10240 + B 8704
#define NSTAGE 4
#define GEMM_SMEM (NSTAGE*SSTAGE)    // 75776

template<int MODE>
__global__ __launch_bounds__(256) void gemm_cp(const float* __restrict__ b1,
                                               const float* __restrict__ b2,
                                               float* __restrict__ Cout)
{
    extern __shared__ unsigned char smem_raw[];
    unsigned smem_u = s2u(smem_raw);

    const uint4* Ag = reinterpret_cast<const uint4*>((MODE==2) ? g_aob : g_lnb);
    const uint4* Bg = reinterpret_cast<const uint4*>((MODE==2) ? g_wob : g_wqkv);
    const int ldn4  = (MODE==2) ? 128 : 384;    // uint4 per weight row

    int tid  = threadIdx.x;
    int lane = tid & 31;
    int warp = tid >> 5;
    int wm = warp >> 2, wn = warp & 3;
    int row0 = blockIdx.y * 128;
    int col0 = blockIdx.x * 128;
    int col4 = col0 >> 3;

    float acc[4][4][4];
    #pragma unroll
    for (int i=0;i<4;i++)
        #pragma unroll
        for (int j=0;j<4;j++)
            #pragma unroll
            for (int e=0;e<4;e++) acc[i][j][e]=0.f;

    const int NKT = 32;

    // ---- prologue: stages 0,1,2
    #pragma unroll
    for (int st=0; st<3; st++){
        unsigned ab = smem_u + st*SSTAGE;
        unsigned bb = ab + 10240;
        #pragma unroll
        for (int i=0;i<2;i++){
            int id = tid + i*256;
            int m = id>>2, c = id&3;
            cpa16(ab + (unsigned)((m*5 + c)*16),
                  Ag + (size_t)(row0+m)*128 + st*4 + c);
            int k = id>>4, c2 = id&15;
            cpa16(bb + (unsigned)((k*17 + c2)*16),
                  Bg + (size_t)(st*32+k)*ldn4 + col4 + c2);
        }
        cpa_commit();
    }
    cpa_wait<2>();
    __syncthreads();

    int buf = 0;
    for (int kt = 0; kt < NKT; kt++){
        unsigned abase = smem_u + buf*SSTAGE;
        unsigned bbase = abase + 10240;
        #pragma unroll
        for (int ks=0; ks<2; ks++){
            unsigned afr[4][4], bfr[2][4];
            #pragma unroll
            for (int mf=0; mf<4; mf++){
                int m0 = wm*64 + mf*16;
                ldsm4(afr[mf], abase +
                      (unsigned)((((m0 + (lane&15))*5) + ks*2 + (lane>>4))*16));
            }
            #pragma unroll
            for (int np=0; np<2; np++){
                ldsm4t(bfr[np], bbase +
                      (unsigned)(((ks*16 + (lane&15))*17 + wn*4 + np*2 + (lane>>4))*16));
            }
            #pragma unroll
            for (int mf=0; mf<4; mf++){
                #pragma unroll
                for (int np=0; np<2; np++){
                    mma_bf16(acc[mf][np*2  ], afr[mf], bfr[np]);
                    mma_bf16(acc[mf][np*2+1], afr[mf], bfr[np]+2);
                }
            }
        }

        if (kt+3 < NKT){
            int ktile = kt+3;
            unsigned ab = smem_u + (unsigned)(((kt+3)%NSTAGE)*SSTAGE);
            unsigned bb2 = ab + 10240;
            #pragma unroll
            for (int i=0;i<2;i++){
                int id = tid + i*256;
                int m = id>>2, c = id&3;
                cpa16(ab + (unsigned)((m*5 + c)*16),
                      Ag + (size_t)(row0+m)*128 + ktile*4 + c);
                int k = id>>4, c2 = id&15;
                cpa16(bb2 + (unsigned)((k*17 + c2)*16),
                      Bg + (size_t)(ktile*32+k)*ldn4 + col4 + c2);
            }
        }
        cpa_commit();
        cpa_wait<2>();
        __syncthreads();
        buf = (buf+1)%NSTAGE;
    }

    // ---- epilogue
    if (MODE == 2){
        #pragma unroll
        for (int mf=0; mf<4; mf++){
            #pragma unroll
            for (int nf=0; nf<4; nf++){
                int c = col0 + wn*32 + nf*8 + 2*(lane&3);
                float2 bia = *reinterpret_cast<const float2*>(b1 + c);
                #pragma unroll
                for (int half=0; half<2; half++){
                    int r = row0 + wm*64 + mf*16 + (lane>>2) + half*8;
                    float2 res = *reinterpret_cast<const float2*>(g_ln + (size_t)r*DM + c);
                    float2 o;
                    o.x = acc[mf][nf][half*2+0] + bia.x + res.x;
                    o.y = acc[mf][nf][half*2+1] + bia.y + res.y;
                    stg_cs_f2(Cout + (size_t)r*DM + c, o);
                }
            }
        }
    } else {
        #pragma unroll
        for (int mf=0; mf<4; mf++){
            #pragma unroll
            for (int nf=0; nf<4; nf++){
                int c = col0 + wn*32 + nf*8 + 2*(lane&3);
                #pragma unroll
                for (int half=0; half<2; half++){
                    int r = row0 + wm*64 + mf*16 + (lane>>2) + half*8;
                    int bb = r >> 10, sIdx = r & 1023;
                    float v0 = acc[mf][nf][half*2+0];
                    float v1 = acc[mf][nf][half*2+1];
                    if (c < 1024){
                        unsigned u = packbf((v0 + b1[c])*QSCL, (v1 + b1[c+1])*QSCL);
                        int h = c>>6, d = c&63;
                        g_qu[(((size_t)(bb*NH+h))*SQL + sIdx)*32 + (d>>1)] = u;
                    } else if (c < 2048){
                        int cc = c-1024;
                        unsigned u = packbf(v0 + b2[cc], v1 + b2[cc+1]);
                        int h = cc>>6, d = cc&63;
                        g_ku[(((size_t)(bb*NH+h))*SQL + sIdx)*32 + (d>>1)] = u;
                    } else {
                        int cc = c-2048;
                        unsigned u = packbf(v0 + b2[cc+1024], v1 + b2[cc+1025]);
                        int h = cc>>6, d = cc&63;
                        g_vu[(((size_t)(bb*NH+h))*SQL + sIdx)*32 + (d>>1)] = u;
                    }
                }
            }
        }
    }
}

// ---------------------------------------------------------------------------
// bf16 flash attention (R9 version + 2 CTAs/SM cap).
// ---------------------------------------------------------------------------
#define ATSTR 36
#define TILE_KV (64*ATSTR)
#define ATT_SMEM (4*TILE_KV*4)             // 2 stages * (K+V) = 36864 B

__global__ void __launch_bounds__(256, 2) attn_bf(const int* __restrict__ lens)
{
    extern __shared__ unsigned sm[];
    unsigned smem_u = s2u(sm);

    int bh = blockIdx.x;
    int qb = (int)(gridDim.y - 1 - blockIdx.y);    // heavy tiles first
    int b  = bh >> 4;
    int h  = bh & 15;
    int tid  = threadIdx.x;
    int lane = tid & 31;
    int w    = tid >> 5;
    int q0   = qb*128;
    int sub  = lane >> 3;
    int rr   = lane & 7;

    const uint4* kg = reinterpret_cast<const uint4*>(g_ku + (size_t)bh*SQL*32);
    const uint4* vg = reinterpret_cast<const uint4*>(g_vu + (size_t)bh*SQL*32);

    int len  = lens[b];
    int kmax = min(q0+127, len-1);
    int nkb  = (kmax>>6) + 1;

    {
        unsigned kb_s = smem_u;
        unsigned vb_s = smem_u + TILE_KV*4;
        #pragma unroll
        for (int i=0;i<2;i++){
            int id = tid + i*256;
            int r = id>>3, c = id&7;
            cpa16(kb_s + (unsigned)((r*ATSTR + c*4)*4), kg + (size_t)r*8 + c);
            cpa16(vb_s + (unsigned)((r*ATSTR + c*4)*4), vg + (size_t)r*8 + c);
        }
        cpa_commit();
    }

    int qrow0 = q0 + w*16 + (lane>>2);
    int qrow1 = qrow0 + 8;

    unsigned aQ[4][4];
    {
        const unsigned* q0p = g_qu + ((size_t)bh*SQL + qrow0)*32;
        const unsigned* q1p = g_qu + ((size_t)bh*SQL + qrow1)*32;
        #pragma unroll
        for (int ks=0; ks<4; ks++){
            aQ[ks][0] = q0p[ks*8 +     (lane&3)];
            aQ[ks][1] = q1p[ks*8 +     (lane&3)];
            aQ[ks][2] = q0p[ks*8 + 4 + (lane&3)];
            aQ[ks][3] = q1p[ks*8 + 4 + (lane&3)];
        }
    }

    float Oacc[8][4];
    #pragma unroll
    for (int i=0;i<8;i++)
        #pragma unroll
        for (int e=0;e<4;e++) Oacc[i][e]=0.f;
    float mi0=-1e30f, mi1=-1e30f, li0=0.f, li1=0.f;

    int buf = 0;
    for (int kb=0; kb<nkb; kb++){
        int k0 = kb*64;
        __syncthreads();
        if (kb+1 < nkb){
            int kn = (kb+1)*64;
            unsigned kb_s = smem_u + (unsigned)((buf^1)*(2*TILE_KV*4));
            unsigned vb_s = kb_s + TILE_KV*4;
            #pragma unroll
            for (int i=0;i<2;i++){
                int id = tid + i*256;
                int r = id>>3, c = id&7;
                cpa16(kb_s + (unsigned)((r*ATSTR + c*4)*4), kg + (size_t)(kn+r)*8 + c);
                cpa16(vb_s + (unsigned)((r*ATSTR + c*4)*4), vg + (size_t)(kn+r)*8 + c);
            }
        }
        cpa_commit();
        cpa_wait<1>();
        __syncthreads();

        unsigned kstage = smem_u + (unsigned)(buf*(2*TILE_KV*4));
        unsigned vstage = kstage + TILE_KV*4;

        float sc[8][4];
        #pragma unroll
        for (int nf=0; nf<8; nf++){
            sc[nf][0]=0.f; sc[nf][1]=0.f; sc[nf][2]=0.f; sc[nf][3]=0.f;
            unsigned kbase_a = kstage + (unsigned)(((nf*8 + rr)*ATSTR + sub*4)*4);
            #pragma unroll
            for (int ksp=0; ksp<2; ksp++){
                unsigned bb4[4];
                ldsm4(bb4, kbase_a + ksp*16*4);
                mma_bf16(sc[nf], aQ[2*ksp  ], bb4);
                mma_bf16(sc[nf], aQ[2*ksp+1], bb4+2);
            }
        }

        if (k0+63 > q0 + w*16 || k0+63 >= len){
            #pragma unroll
            for (int nf=0; nf<8; nf++){
                int jc = k0 + nf*8 + 2*(lane&3);
                #pragma unroll
                for (int e=0; e<4; e++){
                    int j   = jc + (e&1);
                    int row = (e>=2) ? qrow1 : qrow0;
                    sc[nf][e] = (j<=row && j<len) ? sc[nf][e] : -1e30f;
                }
            }
        }

        float rmax0=-1e30f, rmax1=-1e30f;
        #pragma unroll
        for (int nf=0; nf<8; nf++){
            rmax0 = fmaxf(rmax0, fmaxf(sc[nf][0], sc[nf][1]));
            rmax1 = fmaxf(rmax1, fmaxf(sc[nf][2], sc[nf][3]));
        }
        rmax0 = fmaxf(rmax0, __shfl_xor_sync(0xffffffffu, rmax0, 1));
        rmax0 = fmaxf(rmax0, __shfl_xor_sync(0xffffffffu, rmax0, 2));
        rmax1 = fmaxf(rmax1, __shfl_xor_sync(0xffffffffu, rmax1, 1));
        rmax1 = fmaxf(rmax1, __shfl_xor_sync(0xffffffffu, rmax1, 2));

        float mn0 = fmaxf(mi0, rmax0);
        float mn1 = fmaxf(mi1, rmax1);
        float corr0 = ex2f(mi0 - mn0);
        float corr1 = ex2f(mi1 - mn1);
        mi0 = mn0; mi1 = mn1;

        float rs0=0.f, rs1=0.f;
        #pragma unroll
        for (int nf=0; nf<8; nf++){
            sc[nf][0] = ex2f(sc[nf][0]-mn0);
            sc[nf][1] = ex2f(sc[nf][1]-mn0);
            sc[nf][2] = ex2f(sc[nf][2]-mn1);
            sc[nf][3] = ex2f(sc[nf][3]-mn1);
            rs0 += sc[nf][0]+sc[nf][1];
            rs1 += sc[nf][2]+sc[nf][3];
        }
        rs0 += __shfl_xor_sync(0xffffffffu, rs0, 1);
        rs0 += __shfl_xor_sync(0xffffffffu, rs0, 2);
        rs1 += __shfl_xor_sync(0xffffffffu, rs1, 1);
        rs1 += __shfl_xor_sync(0xffffffffu, rs1, 2);
        li0 = li0*corr0 + rs0;
        li1 = li1*corr1 + rs1;

        #pragma unroll
        for (int nf=0; nf<8; nf++){
            Oacc[nf][0]*=corr0; Oacc[nf][1]*=corr0;
            Oacc[nf][2]*=corr1; Oacc[nf][3]*=corr1;
        }

        #pragma unroll
        for (int ks=0; ks<4; ks++){
            unsigned aP[4];
            aP[0] = packbf(sc[2*ks  ][0], sc[2*ks  ][1]);
            aP[1] = packbf(sc[2*ks  ][2], sc[2*ks  ][3]);
            aP[2] = packbf(sc[2*ks+1][0], sc[2*ks+1][1]);
            aP[3] = packbf(sc[2*ks+1][2], sc[2*ks+1][3]);
            unsigned vrow = vstage + (unsigned)(((ks*16 + (sub&1)*8 + rr)*ATSTR + (sub>>1)*4)*4);
            #pragma unroll
            for (int dfp=0; dfp<4; dfp++){
                unsigned bb4[4];
                ldsm4t(bb4, vrow + dfp*8*4);
                mma_bf16(Oacc[2*dfp  ], aP, bb4);
                mma_bf16(Oacc[2*dfp+1], aP, bb4+2);
            }
        }
        buf ^= 1;
    }

    float inv0 = 1.f/li0, inv1 = 1.f/li1;
    unsigned* o0 = g_aob + ((size_t)(b*SQL + qrow0))*512 + h*32;
    unsigned* o1 = g_aob + ((size_t)(b*SQL + qrow1))*512 + h*32;
    #pragma unroll
    for (int df=0; df<8; df++){
        o0[df*4 + (lane&3)] = packbf(Oacc[df][0]*inv0, Oacc[df][1]*inv0);
        o1[df*4 + (lane&3)] = packbf(Oacc[df][2]*inv1, Oacc[df][3]*inv1);
    }
}

// ---------------------------------------------------------------------------
extern "C" void kernel_launch(void* const* d_in, const int* in_sizes, int n_in,
                              void* d_out, int out_size)
{
    const float* x     = (const float*)d_in[0];
    const int*   lens  = (const int*)  d_in[2];
    const float* Wq    = (const float*)d_in[3];
    const float* bq    = (const float*)d_in[4];
    const float* Wkv   = (const float*)d_in[5];
    const float* bkv   = (const float*)d_in[6];
    const float* Wo    = (const float*)d_in[7];
    const float* bo    = (const float*)d_in[8];
    const float* gamma = (const float*)d_in[9];
    const float* beta  = (const float*)d_in[10];
    float* out = (float*)d_out;

    cudaFuncSetAttribute(gemm_cp<0>, cudaFuncAttributeMaxDynamicSharedMemorySize, GEMM_SMEM);
    cudaFuncSetAttribute(gemm_cp<2>, cudaFuncAttributeMaxDynamicSharedMemorySize, GEMM_SMEM);
    cudaFuncSetAttribute(attn_bf,    cudaFuncAttributeMaxDynamicSharedMemorySize, ATT_SMEM);

    prep_kernel<<<NTOK + 4096, 256>>>(x, gamma, beta, Wq, Wkv, Wo);
    gemm_cp<0><<<dim3(24,64), 256, GEMM_SMEM>>>(bq, bkv, nullptr);
    attn_bf   <<<dim3(128,8), 256, ATT_SMEM>>>(lens);
    gemm_cp<2><<<dim3(8, 64), 256, GEMM_SMEM>>>(bo, nullptr, out);
}